// round 4
// baseline (speedup 1.0000x reference)
#include <cuda_runtime.h>

// Problem constants
#define NB    8
#define CIN   2
#define HIN   128
#define WIN   128
#define TT    32
#define CHO   32
#define HP    64
#define WPX   64
#define WPT   32          // wp columns per block
#define NTHR  256         // 8 warps; warp covers 4 wp, lane=(cq, wsub), 4 ch/thread
#define TILE_W 65         // 2*WPT + 1 halo
#define TILE_F (CIN * 3 * TILE_W * TT)            // 12480 floats = 49920 B
#define SMEM_BYTES (TILE_F * 4 + 18 * 8 * 6 * 8)  // tile + weights(48B-strided rows) = 56832

// packed f32x2 fma: d = a*b + d
__device__ __forceinline__ void fma2(unsigned long long &d,
                                     unsigned long long a,
                                     unsigned long long b) {
    asm("fma.rn.f32x2 %0, %1, %2, %3;" : "=l"(d) : "l"(a), "l"(b), "l"(d));
}

__global__ __launch_bounds__(NTHR, 4)
void snn_encoder_kernel(const float* __restrict__ spike,
                        const float* __restrict__ weight_v,
                        const float* __restrict__ weight_g,
                        const float* __restrict__ delay,
                        float* __restrict__ out) {
    extern __shared__ __align__(16) float smem[];
    float* sin_ = smem;                                        // [6][65][32] floats
    unsigned long long* swtq =
        (unsigned long long*)(smem + TILE_F);                  // [(k*8+cq)*6 + s] (48B rows)

    const int tid  = threadIdx.x;
    const int lane = tid & 31;
    const int wid  = tid >> 5;        // warp 0..7
    const int cq   = lane & 7;        // channel quarter: ch = cq + 8*s, s=0..3
    const int wsub = lane >> 3;       // phase-aligned -> tap loads broadcast per phase
    const int wpl  = 4 * wid + wsub;  // 0..31 local wp
    const int wp0  = blockIdx.x * WPT;
    const int hp   = blockIdx.y;
    const int n    = blockIdx.z;

    // ---- weight norm (one thread per output channel) ----
    if (tid < 32) {
        float wv[18];
        float ss = 0.f;
        #pragma unroll
        for (int k = 0; k < 18; k++) {
            wv[k] = weight_v[tid * 18 + k];
            ss += wv[k] * wv[k];
        }
        const float sc = weight_g[tid] / sqrtf(ss);
        const int col = tid & 7, s = tid >> 3;
        #pragma unroll
        for (int k = 0; k < 18; k++) {
            const unsigned int wu = __float_as_uint(wv[k] * sc);
            swtq[(k * 8 + col) * 6 + s] = ((unsigned long long)wu << 32) | wu;
        }
    }

    // ---- cooperative input tile load (fully coalesced; (w,t) contiguous) ----
    const int h0 = 2 * hp - 1;
    const int w0 = 2 * wp0 - 1;
    for (int idx = tid; idx < CIN * 3 * TILE_W * 8; idx += NTHR) {
        const int plane = idx / (TILE_W * 8);       // c*3 + r
        const int rem   = idx - plane * (TILE_W * 8);
        const int wj    = rem >> 3;
        const int t4    = rem & 7;
        const int c = plane / 3;
        const int r = plane - c * 3;
        const int h = h0 + r;
        const int w = w0 + wj;
        float4 v = make_float4(0.f, 0.f, 0.f, 0.f);
        if ((unsigned)h < HIN && (unsigned)w < WIN) {
            v = *(const float4*)(spike +
                (((size_t)(n * CIN + c) * HIN + h) * WIN + w) * TT + t4 * 4);
        }
        *(float4*)(sin_ + (plane * TILE_W + wj) * TT + t4 * 4) = v;
    }
    __syncthreads();

    // ---- conv (f32x2, 4 ch/thread share each tap load) + LIF scan ----
    float cur[4]  = {0.f, 0.f, 0.f, 0.f};
    float volt[4] = {0.f, 0.f, 0.f, 0.f};
    unsigned int bits[4] = {0u, 0u, 0u, 0u};

    const unsigned long long* wbase = swtq + cq * 6;

    #pragma unroll
    for (int chunk = 0; chunk < 4; chunk++) {
        unsigned long long z[4][4];
        #pragma unroll
        for (int s = 0; s < 4; s++)
            #pragma unroll
            for (int q = 0; q < 4; q++) z[s][q] = 0ull;

        #pragma unroll
        for (int c = 0; c < CIN; c++) {
            #pragma unroll
            for (int r = 0; r < 3; r++) {
                #pragma unroll
                for (int kw = 0; kw < 3; kw++) {
                    const int k = c * 9 + r * 3 + kw;
                    const float* tp = sin_ +
                        ((c * 3 + r) * TILE_W + 2 * wpl + kw) * TT + chunk * 8;
                    const ulonglong2 a = *(const ulonglong2*)tp;        // t pairs 0,1
                    const ulonglong2 b = *(const ulonglong2*)(tp + 4);  // t pairs 2,3
                    const ulonglong2 w01 = *(const ulonglong2*)(wbase + k * 48);
                    const ulonglong2 w23 = *(const ulonglong2*)(wbase + k * 48 + 2);
                    fma2(z[0][0], a.x, w01.x); fma2(z[0][1], a.y, w01.x);
                    fma2(z[0][2], b.x, w01.x); fma2(z[0][3], b.y, w01.x);
                    fma2(z[1][0], a.x, w01.y); fma2(z[1][1], a.y, w01.y);
                    fma2(z[1][2], b.x, w01.y); fma2(z[1][3], b.y, w01.y);
                    fma2(z[2][0], a.x, w23.x); fma2(z[2][1], a.y, w23.x);
                    fma2(z[2][2], b.x, w23.x); fma2(z[2][3], b.y, w23.x);
                    fma2(z[3][0], a.x, w23.y); fma2(z[3][1], a.y, w23.y);
                    fma2(z[3][2], b.x, w23.y); fma2(z[3][3], b.y, w23.y);
                }
            }
        }
        // LIF over 8 timesteps for 4 independent channels (ILP)
        #pragma unroll
        for (int q = 0; q < 4; q++) {
            const int t = chunk * 8 + q * 2;
            #pragma unroll
            for (int s = 0; s < 4; s++) {
                const float zl = __uint_as_float((unsigned)(z[s][q] & 0xffffffffull));
                const float zh = __uint_as_float((unsigned)(z[s][q] >> 32));
                cur[s]  = cur[s] * 0.75f + zl;
                volt[s] = volt[s] * 0.9f + cur[s];
                if (volt[s] >= 1.0f) { bits[s] |= 1u << t; volt[s] = 0.f; }
                cur[s]  = cur[s] * 0.75f + zh;
                volt[s] = volt[s] * 0.9f + cur[s];
                if (volt[s] >= 1.0f) { bits[s] |= 1u << (t + 1); volt[s] = 0.f; }
            }
        }
    }

    // ---- transpose spike masks through (recycled) smem ----
    __syncthreads();                       // tile reads done; reuse as sbits[32][33]
    unsigned int* sb = (unsigned int*)sin_;
    #pragma unroll
    for (int s = 0; s < 4; s++)
        sb[(cq + 8 * s) * 33 + wpl] = bits[s];
    __syncthreads();

    // ---- coalesced epilogue: warp wid writes channels wid + 8*sp ----
    #pragma unroll
    for (int sp = 0; sp < 4; sp++) {
        const int ch = wid + 8 * sp;
        const float d  = delay[ch];
        const int   di = (int)floorf(d);
        const float f  = d - (float)di;
        const float onef = 1.0f - f;
        float* obase = out +
            (((size_t)((n * CHO + ch) * HP + hp) * WPX + wp0) * TT);
        #pragma unroll
        for (int i = 0; i < 8; i++) {
            const int idx = i * 32 + lane;         // 0..255 float4 slots (32wp x 8)
            const int wpi = idx >> 3;
            const int t   = (idx & 7) * 4;
            const unsigned int bt = sb[ch * 33 + wpi];
            unsigned int b0 = 0u, b1 = 0u;
            if (di >= 0 && di < 32)         b0 = bt << di;
            if (di + 1 >= 0 && di + 1 < 32) b1 = bt << (di + 1);
            float4 v;
            v.x = onef * (float)((b0 >> (t + 0)) & 1u) + f * (float)((b1 >> (t + 0)) & 1u);
            v.y = onef * (float)((b0 >> (t + 1)) & 1u) + f * (float)((b1 >> (t + 1)) & 1u);
            v.z = onef * (float)((b0 >> (t + 2)) & 1u) + f * (float)((b1 >> (t + 2)) & 1u);
            v.w = onef * (float)((b0 >> (t + 3)) & 1u) + f * (float)((b1 >> (t + 3)) & 1u);
            *(float4*)(obase + idx * 4) = v;
        }
    }
}

extern "C" void kernel_launch(void* const* d_in, const int* in_sizes, int n_in,
                              void* d_out, int out_size) {
    const float* spike    = (const float*)d_in[0];
    const float* weight_v = (const float*)d_in[1];
    const float* weight_g = (const float*)d_in[2];
    const float* delay    = (const float*)d_in[3];
    float* out = (float*)d_out;

    cudaFuncSetAttribute(snn_encoder_kernel,
                         cudaFuncAttributeMaxDynamicSharedMemorySize, SMEM_BYTES);
    dim3 grid(WPX / WPT, HP, NB);   // (2, 64, 8) = 1024 blocks
    snn_encoder_kernel<<<grid, NTHR, SMEM_BYTES>>>(spike, weight_v, weight_g, delay, out);
}

// round 5
// speedup vs baseline: 1.5299x; 1.5299x over previous
#include <cuda_runtime.h>

// Problem constants
#define NB     8
#define CIN    2
#define HIN    128
#define WIN    128
#define TT     32
#define CHO    32
#define HP     64
#define WPX    64
#define WPT    32          // wp columns per block (16 warps x 2 wp)
#define NTHR   512
#define TILE_W 65          // 2*WPT + 1 halo
#define TILE_F (CIN * 3 * TILE_W * TT)               // 12480 floats = 49920 B
#define WT_OFF TILE_F                                 // weights after tile
#define SMEM_BYTES (TILE_F * 4 + 18 * 16 * 2 * 8)     // 49920 + 4608 = 54528

// packed f32x2 fma: d = a*b + d
__device__ __forceinline__ void fma2(unsigned long long &d,
                                     unsigned long long a,
                                     unsigned long long b) {
    asm("fma.rn.f32x2 %0, %1, %2, %3;" : "=l"(d) : "l"(a), "l"(b), "l"(d));
}

__global__ __launch_bounds__(NTHR, 2)
void snn_encoder_kernel(const float* __restrict__ spike,
                        const float* __restrict__ weight_v,
                        const float* __restrict__ weight_g,
                        const float* __restrict__ delay,
                        float* __restrict__ out) {
    extern __shared__ __align__(16) float smem[];
    float* sin_ = smem;                                      // [6][65][32] floats
    unsigned long long* swt2 = (unsigned long long*)(smem + WT_OFF);
    // swt2 layout: [(k*16 + c2)*2 + half] = dup(w[c2 + 16*half]) for tap k

    const int tid  = threadIdx.x;
    const int lane = tid & 31;
    const int wid  = tid >> 5;        // warp 0..15
    const int c2   = lane & 15;       // channels c2 and c2+16
    const int wsub = lane >> 4;       // half-warp -> second wp column
    const int wpl  = 2 * wid + wsub;  // 0..31 local wp (quarter-warp phase aligned)
    const int wp0  = blockIdx.x * WPT;
    const int hp   = blockIdx.y;
    const int n    = blockIdx.z;

    // ---- weight norm (one thread per output channel) ----
    if (tid < 32) {
        float wv[18];
        float ss = 0.f;
        #pragma unroll
        for (int k = 0; k < 18; k++) {
            wv[k] = weight_v[tid * 18 + k];
            ss += wv[k] * wv[k];
        }
        const float sc = weight_g[tid] / sqrtf(ss);
        const int col = tid & 15, half = tid >> 4;
        #pragma unroll
        for (int k = 0; k < 18; k++) {
            const unsigned int wu = __float_as_uint(wv[k] * sc);
            swt2[(k * 16 + col) * 2 + half] = ((unsigned long long)wu << 32) | wu;
        }
    }

    // ---- cooperative input tile load (fully coalesced; (w,t) contiguous) ----
    const int h0 = 2 * hp - 1;
    const int w0 = 2 * wp0 - 1;
    for (int idx = tid; idx < CIN * 3 * TILE_W * 8; idx += NTHR) {
        const int plane = idx / (TILE_W * 8);        // c*3 + r
        const int rem   = idx - plane * (TILE_W * 8);
        const int wj    = rem >> 3;
        const int t4    = rem & 7;
        const int c = plane / 3;
        const int r = plane - c * 3;
        const int h = h0 + r;
        const int w = w0 + wj;
        float4 v = make_float4(0.f, 0.f, 0.f, 0.f);
        if ((unsigned)h < HIN && (unsigned)w < WIN) {
            v = *(const float4*)(spike +
                (((size_t)(n * CIN + c) * HIN + h) * WIN + w) * TT + t4 * 4);
        }
        *(float4*)(sin_ + (plane * TILE_W + wj) * TT + t4 * 4) = v;
    }
    __syncthreads();

    // ---- conv (f32x2, 2 ch/thread share tap loads) + LIF scan ----
    float cur0 = 0.f, volt0 = 0.f, cur1 = 0.f, volt1 = 0.f;
    unsigned int bits0 = 0u, bits1 = 0u;

    const float* tapbase = sin_ + 2 * wpl * TT;

    #pragma unroll
    for (int chunk = 0; chunk < 4; chunk++) {
        unsigned long long za[4] = {0ull, 0ull, 0ull, 0ull};   // channel c2
        unsigned long long zb[4] = {0ull, 0ull, 0ull, 0ull};   // channel c2+16
        #pragma unroll
        for (int c = 0; c < CIN; c++) {
            #pragma unroll
            for (int r = 0; r < 3; r++) {
                #pragma unroll
                for (int kw = 0; kw < 3; kw++) {
                    const int k = c * 9 + r * 3 + kw;
                    const float* tp = tapbase +
                        ((c * 3 + r) * TILE_W + kw) * TT + chunk * 8;
                    const ulonglong2 a  = *(const ulonglong2*)tp;        // t 0..3
                    const ulonglong2 b  = *(const ulonglong2*)(tp + 4);  // t 4..7
                    const ulonglong2 w2 = *(const ulonglong2*)&swt2[(k * 16 + c2) * 2];
                    fma2(za[0], a.x, w2.x);  fma2(zb[0], a.x, w2.y);
                    fma2(za[1], a.y, w2.x);  fma2(zb[1], a.y, w2.y);
                    fma2(za[2], b.x, w2.x);  fma2(zb[2], b.x, w2.y);
                    fma2(za[3], b.y, w2.x);  fma2(zb[3], b.y, w2.y);
                }
            }
        }
        // LIF over 8 timesteps, 2 independent channels, select-based (no pred guards)
        #pragma unroll
        for (int j = 0; j < 4; j++) {
            const int t = chunk * 8 + j * 2;
            const float za_l = __uint_as_float((unsigned)(za[j] & 0xffffffffull));
            const float za_h = __uint_as_float((unsigned)(za[j] >> 32));
            const float zb_l = __uint_as_float((unsigned)(zb[j] & 0xffffffffull));
            const float zb_h = __uint_as_float((unsigned)(zb[j] >> 32));

            cur0  = cur0 * 0.75f + za_l;
            cur1  = cur1 * 0.75f + zb_l;
            volt0 = volt0 * 0.9f + cur0;
            volt1 = volt1 * 0.9f + cur1;
            { const bool s0 = volt0 >= 1.0f, s1 = volt1 >= 1.0f;
              bits0 |= s0 ? (1u << t) : 0u;  volt0 = s0 ? 0.f : volt0;
              bits1 |= s1 ? (1u << t) : 0u;  volt1 = s1 ? 0.f : volt1; }

            cur0  = cur0 * 0.75f + za_h;
            cur1  = cur1 * 0.75f + zb_h;
            volt0 = volt0 * 0.9f + cur0;
            volt1 = volt1 * 0.9f + cur1;
            { const bool s0 = volt0 >= 1.0f, s1 = volt1 >= 1.0f;
              bits0 |= s0 ? (1u << (t + 1)) : 0u;  volt0 = s0 ? 0.f : volt0;
              bits1 |= s1 ? (1u << (t + 1)) : 0u;  volt1 = s1 ? 0.f : volt1; }
        }
    }

    // ---- transpose spike masks through recycled tile smem ----
    __syncthreads();                         // tile reads done
    unsigned int* sb = (unsigned int*)sin_;  // sbits[32][33]
    sb[c2 * 33 + wpl]        = bits0;
    sb[(c2 + 16) * 33 + wpl] = bits1;
    __syncthreads();

    // ---- coalesced epilogue: warp wid writes channels wid and wid+16 ----
    #pragma unroll
    for (int half = 0; half < 2; half++) {
        const int ch = wid + 16 * half;
        const float d  = delay[ch];               // warp-uniform
        const int   di = (int)floorf(d);
        const float f  = d - (float)di;
        const float onef = 1.0f - f;
        float* obase = out +
            (((size_t)((n * CHO + ch) * HP + hp) * WPX + wp0) * TT);
        #pragma unroll
        for (int i = 0; i < 8; i++) {
            const int idx = i * 32 + lane;        // 0..255 float4 slots (32wp x 8)
            const int wpi = idx >> 3;
            const int t   = (idx & 7) * 4;
            const unsigned int bt = sb[ch * 33 + wpi];
            unsigned int b0 = 0u, b1 = 0u;
            if (di >= 0 && di < 32)         b0 = bt << di;
            if (di + 1 >= 0 && di + 1 < 32) b1 = bt << (di + 1);
            float4 v;
            v.x = onef * (float)((b0 >> (t + 0)) & 1u) + f * (float)((b1 >> (t + 0)) & 1u);
            v.y = onef * (float)((b0 >> (t + 1)) & 1u) + f * (float)((b1 >> (t + 1)) & 1u);
            v.z = onef * (float)((b0 >> (t + 2)) & 1u) + f * (float)((b1 >> (t + 2)) & 1u);
            v.w = onef * (float)((b0 >> (t + 3)) & 1u) + f * (float)((b1 >> (t + 3)) & 1u);
            *(float4*)(obase + idx * 4) = v;
        }
    }
}

extern "C" void kernel_launch(void* const* d_in, const int* in_sizes, int n_in,
                              void* d_out, int out_size) {
    const float* spike    = (const float*)d_in[0];
    const float* weight_v = (const float*)d_in[1];
    const float* weight_g = (const float*)d_in[2];
    const float* delay    = (const float*)d_in[3];
    float* out = (float*)d_out;

    cudaFuncSetAttribute(snn_encoder_kernel,
                         cudaFuncAttributeMaxDynamicSharedMemorySize, SMEM_BYTES);
    dim3 grid(WPX / WPT, HP, NB);   // (2, 64, 8) = 1024 blocks
    snn_encoder_kernel<<<grid, NTHR, SMEM_BYTES>>>(spike, weight_v, weight_g, delay, out);
}

// round 6
// speedup vs baseline: 1.6211x; 1.0596x over previous
#include <cuda_runtime.h>

// Problem constants
#define NB     8
#define CIN    2
#define HIN    128
#define WIN    128
#define TT     32
#define CHO    32
#define HP     64
#define WPX    64
#define WPT    32          // wp columns per block (16 warps x 2 wp)
#define NTHR   512
#define TILE_W 65          // 2*WPT + 1 halo
#define TILE_F (CIN * 3 * TILE_W * TT)               // 12480 floats = 49920 B
#define WT_OFF TILE_F                                 // weights after tile
#define SMEM_BYTES (TILE_F * 4 + 18 * 16 * 2 * 8)     // 49920 + 4608 = 54528

// packed f32x2 fma: d = a*b + d
__device__ __forceinline__ void fma2(unsigned long long &d,
                                     unsigned long long a,
                                     unsigned long long b) {
    asm("fma.rn.f32x2 %0, %1, %2, %3;" : "=l"(d) : "l"(a), "l"(b), "l"(d));
}

__global__ __launch_bounds__(NTHR, 2)
void snn_encoder_kernel(const float* __restrict__ spike,
                        const float* __restrict__ weight_v,
                        const float* __restrict__ weight_g,
                        const float* __restrict__ delay,
                        float* __restrict__ out) {
    extern __shared__ __align__(16) float smem[];
    float* sin_ = smem;                                      // [6][65][32] floats
    unsigned long long* swt2 = (unsigned long long*)(smem + WT_OFF);
    // swt2 layout: [(k*16 + c2)*2 + half] = dup(w[c2 + 16*half]) for tap k

    const int tid  = threadIdx.x;
    const int lane = tid & 31;
    const int wid  = tid >> 5;        // warp 0..15
    const int c2   = lane & 15;       // channels c2 and c2+16
    const int wsub = lane >> 4;       // half-warp -> second wp column
    const int wpl  = 2 * wid + wsub;  // 0..31 local wp
    const int wp0  = blockIdx.x * WPT;
    const int hp   = blockIdx.y;
    const int n    = blockIdx.z;

    // ---- weight norm (one thread per output channel) ----
    if (tid < 32) {
        float wv[18];
        float ss = 0.f;
        #pragma unroll
        for (int k = 0; k < 18; k++) {
            wv[k] = weight_v[tid * 18 + k];
            ss += wv[k] * wv[k];
        }
        const float sc = weight_g[tid] / sqrtf(ss);
        const int col = tid & 15, half = tid >> 4;
        #pragma unroll
        for (int k = 0; k < 18; k++) {
            const unsigned int wu = __float_as_uint(wv[k] * sc);
            swt2[(k * 16 + col) * 2 + half] = ((unsigned long long)wu << 32) | wu;
        }
    }

    // ---- cooperative input tile load (fully coalesced; (w,t) contiguous) ----
    const int h0 = 2 * hp - 1;
    const int w0 = 2 * wp0 - 1;
    for (int idx = tid; idx < CIN * 3 * TILE_W * 8; idx += NTHR) {
        const int plane = idx / (TILE_W * 8);        // c*3 + r
        const int rem   = idx - plane * (TILE_W * 8);
        const int wj    = rem >> 3;
        const int t4    = rem & 7;
        const int c = plane / 3;
        const int r = plane - c * 3;
        const int h = h0 + r;
        const int w = w0 + wj;
        float4 v = make_float4(0.f, 0.f, 0.f, 0.f);
        if ((unsigned)h < HIN && (unsigned)w < WIN) {
            v = *(const float4*)(spike +
                (((size_t)(n * CIN + c) * HIN + h) * WIN + w) * TT + t4 * 4);
        }
        *(float4*)(sin_ + (plane * TILE_W + wj) * TT + t4 * 4) = v;
    }
    __syncthreads();

    // ---- conv (f32x2, 2 ch/thread share tap loads) + LIF scan ----
    // chunk loop deliberately NOT unrolled: keeps the 18 ulonglong2 weight
    // loads inside the loop so ptxas cannot hoist 72 regs of weights and
    // spill the accumulators (the round-4/5 DRAM blowup).
    float cur0 = 0.f, volt0 = 0.f, cur1 = 0.f, volt1 = 0.f;
    unsigned int bits0 = 0u, bits1 = 0u;

    const float* tapbase = sin_ + 2 * wpl * TT;

    #pragma unroll 1
    for (int chunk = 0; chunk < 4; chunk++) {
        unsigned long long za[4] = {0ull, 0ull, 0ull, 0ull};   // channel c2
        unsigned long long zb[4] = {0ull, 0ull, 0ull, 0ull};   // channel c2+16
        #pragma unroll
        for (int c = 0; c < CIN; c++) {
            #pragma unroll
            for (int r = 0; r < 3; r++) {
                #pragma unroll
                for (int kw = 0; kw < 3; kw++) {
                    const int k = c * 9 + r * 3 + kw;
                    const float* tp = tapbase +
                        ((c * 3 + r) * TILE_W + kw) * TT + chunk * 8;
                    const ulonglong2 a  = *(const ulonglong2*)tp;        // t 0..3
                    const ulonglong2 b  = *(const ulonglong2*)(tp + 4);  // t 4..7
                    const ulonglong2 w2 = *(const ulonglong2*)&swt2[(k * 16 + c2) * 2];
                    fma2(za[0], a.x, w2.x);  fma2(zb[0], a.x, w2.y);
                    fma2(za[1], a.y, w2.x);  fma2(zb[1], a.y, w2.y);
                    fma2(za[2], b.x, w2.x);  fma2(zb[2], b.x, w2.y);
                    fma2(za[3], b.y, w2.x);  fma2(zb[3], b.y, w2.y);
                }
            }
        }
        // LIF over 8 timesteps, 2 independent channels, select-based
        #pragma unroll
        for (int j = 0; j < 4; j++) {
            const int t = chunk * 8 + j * 2;
            const float za_l = __uint_as_float((unsigned)(za[j] & 0xffffffffull));
            const float za_h = __uint_as_float((unsigned)(za[j] >> 32));
            const float zb_l = __uint_as_float((unsigned)(zb[j] & 0xffffffffull));
            const float zb_h = __uint_as_float((unsigned)(zb[j] >> 32));

            cur0  = cur0 * 0.75f + za_l;
            cur1  = cur1 * 0.75f + zb_l;
            volt0 = volt0 * 0.9f + cur0;
            volt1 = volt1 * 0.9f + cur1;
            { const bool s0 = volt0 >= 1.0f, s1 = volt1 >= 1.0f;
              bits0 |= s0 ? (1u << t) : 0u;  volt0 = s0 ? 0.f : volt0;
              bits1 |= s1 ? (1u << t) : 0u;  volt1 = s1 ? 0.f : volt1; }

            cur0  = cur0 * 0.75f + za_h;
            cur1  = cur1 * 0.75f + zb_h;
            volt0 = volt0 * 0.9f + cur0;
            volt1 = volt1 * 0.9f + cur1;
            { const bool s0 = volt0 >= 1.0f, s1 = volt1 >= 1.0f;
              bits0 |= s0 ? (1u << (t + 1)) : 0u;  volt0 = s0 ? 0.f : volt0;
              bits1 |= s1 ? (1u << (t + 1)) : 0u;  volt1 = s1 ? 0.f : volt1; }
        }
    }

    // ---- transpose spike masks through recycled tile smem ----
    __syncthreads();                         // tile reads done
    unsigned int* sb = (unsigned int*)sin_;  // sbits[32][33]
    sb[c2 * 33 + wpl]        = bits0;
    sb[(c2 + 16) * 33 + wpl] = bits1;
    __syncthreads();

    // ---- coalesced epilogue: warp wid writes channels wid and wid+16 ----
    #pragma unroll
    for (int half = 0; half < 2; half++) {
        const int ch = wid + 16 * half;
        const float d  = delay[ch];               // warp-uniform
        const int   di = (int)floorf(d);
        const float f  = d - (float)di;
        const float onef = 1.0f - f;
        float* obase = out +
            (((size_t)((n * CHO + ch) * HP + hp) * WPX + wp0) * TT);
        #pragma unroll
        for (int i = 0; i < 8; i++) {
            const int idx = i * 32 + lane;        // 0..255 float4 slots (32wp x 8)
            const int wpi = idx >> 3;
            const int t   = (idx & 7) * 4;
            const unsigned int bt = sb[ch * 33 + wpi];
            unsigned int b0 = 0u, b1 = 0u;
            if (di >= 0 && di < 32)         b0 = bt << di;
            if (di + 1 >= 0 && di + 1 < 32) b1 = bt << (di + 1);
            float4 v;
            v.x = onef * (float)((b0 >> (t + 0)) & 1u) + f * (float)((b1 >> (t + 0)) & 1u);
            v.y = onef * (float)((b0 >> (t + 1)) & 1u) + f * (float)((b1 >> (t + 1)) & 1u);
            v.z = onef * (float)((b0 >> (t + 2)) & 1u) + f * (float)((b1 >> (t + 2)) & 1u);
            v.w = onef * (float)((b0 >> (t + 3)) & 1u) + f * (float)((b1 >> (t + 3)) & 1u);
            *(float4*)(obase + idx * 4) = v;
        }
    }
}

extern "C" void kernel_launch(void* const* d_in, const int* in_sizes, int n_in,
                              void* d_out, int out_size) {
    const float* spike    = (const float*)d_in[0];
    const float* weight_v = (const float*)d_in[1];
    const float* weight_g = (const float*)d_in[2];
    const float* delay    = (const float*)d_in[3];
    float* out = (float*)d_out;

    cudaFuncSetAttribute(snn_encoder_kernel,
                         cudaFuncAttributeMaxDynamicSharedMemorySize, SMEM_BYTES);
    dim3 grid(WPX / WPT, HP, NB);   // (2, 64, 8) = 1024 blocks
    snn_encoder_kernel<<<grid, NTHR, SMEM_BYTES>>>(spike, weight_v, weight_g, delay, out);
}

// round 7
// speedup vs baseline: 2.0909x; 1.2898x over previous
#include <cuda_runtime.h>

// Problem constants
#define NB     8
#define CIN    2
#define HIN    128
#define WIN    128
#define TT     32
#define CHO    32
#define HP     64
#define WPX    64
#define WPT    16            // wp columns per block
#define NTHR   256           // 8 warps; conv: warp = 4 channels, lane = t
#define TILE_W 33            // 2*WPT + 1 halo

// smem layout (floats)
#define TILE_F  (CIN * 3 * TILE_W * TT)      // 6336  : input tile [6][33][32]
#define ZROW    33                            // padded t-row (bank-conflict-free)
#define Z_OFF   TILE_F                        // z[32ch*16wp][33]
#define Z_F     (CHO * WPT * ZROW)            // 16896
#define SW_OFF  (Z_OFF + Z_F)                 // weights [18][32]
#define SW_F    (18 * CHO)                    // 576
#define SMEM_BYTES ((SW_OFF + SW_F) * 4)      // 95232 B

__global__ __launch_bounds__(NTHR, 2)
void snn_encoder_kernel(const float* __restrict__ spike,
                        const float* __restrict__ weight_v,
                        const float* __restrict__ weight_g,
                        const float* __restrict__ delay,
                        float* __restrict__ out) {
    extern __shared__ __align__(16) float smem[];
    float* sin_ = smem;              // [plane(6)][w(33)][t(32)]
    float* zbuf = smem + Z_OFF;      // [(ch*16+wp)][33]
    float* sw   = smem + SW_OFF;     // [tap(18)][ch(32)]

    const int tid  = threadIdx.x;
    const int lane = tid & 31;       // conv phase: lane = t
    const int wid  = tid >> 5;       // warp 0..7: channels 4*wid .. 4*wid+3
    const int wp0  = blockIdx.x * WPT;
    const int hp   = blockIdx.y;
    const int n    = blockIdx.z;

    // ---- weight norm (one thread per output channel) ----
    if (tid < 32) {
        float wv[18];
        float ss = 0.f;
        #pragma unroll
        for (int k = 0; k < 18; k++) {
            wv[k] = weight_v[tid * 18 + k];
            ss += wv[k] * wv[k];
        }
        const float sc = weight_g[tid] / sqrtf(ss);
        #pragma unroll
        for (int k = 0; k < 18; k++)
            sw[k * 32 + tid] = wv[k] * sc;
    }

    // ---- cooperative input tile load (coalesced; (w,t) contiguous) ----
    const int h0 = 2 * hp - 1;
    const int w0 = 2 * wp0 - 1;
    for (int idx = tid; idx < CIN * 3 * TILE_W * 8; idx += NTHR) {
        const int plane = idx / (TILE_W * 8);        // c*3 + r
        const int rem   = idx - plane * (TILE_W * 8);
        const int wj    = rem >> 3;
        const int t4    = rem & 7;
        const int c = plane / 3;
        const int r = plane - c * 3;
        const int h = h0 + r;
        const int w = w0 + wj;
        float4 v = make_float4(0.f, 0.f, 0.f, 0.f);
        if ((unsigned)h < HIN && (unsigned)w < WIN) {
            v = *(const float4*)(spike +
                (((size_t)(n * CIN + c) * HIN + h) * WIN + w) * TT + t4 * 4);
        }
        *(float4*)(sin_ + (plane * TILE_W + wj) * TT + t4 * 4) = v;
    }
    __syncthreads();

    // ---- PHASE 1: conv, weight-stationary. warp = 4 ch, lane = t ----
    // 72 scalar weight regs hoisted once; accumulators are only 4 regs,
    // so total live ~100 regs < 128 cap (launch_bounds 256,2): no spill.
    {
        float wr[18][4];
        #pragma unroll
        for (int k = 0; k < 18; k++) {
            const float4 wv4 = *(const float4*)(sw + k * 32 + 4 * wid);
            wr[k][0] = wv4.x; wr[k][1] = wv4.y; wr[k][2] = wv4.z; wr[k][3] = wv4.w;
        }
        const float* tbase = sin_ + lane;
        #pragma unroll 2
        for (int wp = 0; wp < WPT; wp++) {
            float a0 = 0.f, a1 = 0.f, a2 = 0.f, a3 = 0.f;
            #pragma unroll
            for (int c = 0; c < CIN; c++) {
                #pragma unroll
                for (int r = 0; r < 3; r++) {
                    #pragma unroll
                    for (int kw = 0; kw < 3; kw++) {
                        const int k = c * 9 + r * 3 + kw;
                        const float tap =
                            tbase[((c * 3 + r) * TILE_W + 2 * wp + kw) * TT];
                        a0 += tap * wr[k][0];
                        a1 += tap * wr[k][1];
                        a2 += tap * wr[k][2];
                        a3 += tap * wr[k][3];
                    }
                }
            }
            float* zr = zbuf + ((4 * wid) * WPT + wp) * ZROW + lane;
            zr[0 * WPT * ZROW] = a0;
            zr[1 * WPT * ZROW] = a1;
            zr[2 * WPT * ZROW] = a2;
            zr[3 * WPT * ZROW] = a3;
        }
    }
    __syncthreads();

    // ---- PHASE 2: LIF scan, t-in-thread; 2 (ch,wp) pairs per thread ----
    unsigned int* sb = (unsigned int*)sin_;   // sbits[ch*16+wp], aliases dead tile
    #pragma unroll
    for (int pp = 0; pp < 2; pp++) {
        const int p = tid + pp * NTHR;        // 0..511 = ch*16 + wp
        const float* zr = zbuf + p * ZROW;
        float cur = 0.f, volt = 0.f;
        unsigned int bits = 0u;
        #pragma unroll
        for (int t = 0; t < TT; t++) {
            cur  = cur * 0.75f + zr[t];
            volt = volt * 0.9f + cur;
            const bool s = volt >= 1.0f;
            bits |= s ? (1u << t) : 0u;
            volt  = s ? 0.f : volt;
        }
        sb[p] = bits;
    }
    __syncthreads();

    // ---- PHASE 3: coalesced epilogue. warp wid writes ch wid+8*sp ----
    #pragma unroll
    for (int sp = 0; sp < 4; sp++) {
        const int ch = wid + 8 * sp;
        const float d  = delay[ch];           // warp-uniform
        const int   di = (int)floorf(d);
        const float f  = d - (float)di;
        const float onef = 1.0f - f;
        float* obase = out +
            (((size_t)((n * CHO + ch) * HP + hp) * WPX + wp0) * TT);
        #pragma unroll
        for (int i = 0; i < 4; i++) {
            const int idx = i * 32 + lane;    // 0..127 float4 slots (16wp x 8)
            const int wpi = idx >> 3;
            const int t   = (idx & 7) * 4;
            const unsigned int bt = sb[ch * WPT + wpi];
            unsigned int b0 = 0u, b1 = 0u;
            if (di >= 0 && di < 32)         b0 = bt << di;
            if (di + 1 >= 0 && di + 1 < 32) b1 = bt << (di + 1);
            float4 v;
            v.x = onef * (float)((b0 >> (t + 0)) & 1u) + f * (float)((b1 >> (t + 0)) & 1u);
            v.y = onef * (float)((b0 >> (t + 1)) & 1u) + f * (float)((b1 >> (t + 1)) & 1u);
            v.z = onef * (float)((b0 >> (t + 2)) & 1u) + f * (float)((b1 >> (t + 2)) & 1u);
            v.w = onef * (float)((b0 >> (t + 3)) & 1u) + f * (float)((b1 >> (t + 3)) & 1u);
            *(float4*)(obase + idx * 4) = v;
        }
    }
}

extern "C" void kernel_launch(void* const* d_in, const int* in_sizes, int n_in,
                              void* d_out, int out_size) {
    const float* spike    = (const float*)d_in[0];
    const float* weight_v = (const float*)d_in[1];
    const float* weight_g = (const float*)d_in[2];
    const float* delay    = (const float*)d_in[3];
    float* out = (float*)d_out;

    cudaFuncSetAttribute(snn_encoder_kernel,
                         cudaFuncAttributeMaxDynamicSharedMemorySize, SMEM_BYTES);
    dim3 grid(WPX / WPT, HP, NB);   // (4, 64, 8) = 2048 blocks
    snn_encoder_kernel<<<grid, NTHR, SMEM_BYTES>>>(spike, weight_v, weight_g, delay, out);
}

// round 9
// speedup vs baseline: 2.2375x; 1.0701x over previous
#include <cuda_runtime.h>

// Problem constants
#define NB     8
#define CIN    2
#define HIN    128
#define WIN    128
#define TT     32
#define CHO    32
#define HP     64
#define WPX    64
#define WPT    16            // wp columns per block
#define NTHR   512           // 16 warps; conv: warp = 2 ch, lane = (t-pair, wp-parity)
#define TILE_W 33            // 2*WPT + 1 halo

// smem layout (floats)
#define TILE_F  (CIN * 3 * TILE_W * TT)      // 6336  : input tile [6][33][32]
#define ZROW    36                            // padded t-row: 144 B (16B-aligned rows,
                                              // stride 4 banks -> conflict-free LDS.128)
#define Z_OFF   TILE_F                        // z[32ch*16wp][36]
#define Z_F     (CHO * WPT * ZROW)            // 18432
#define SW_OFF  (Z_OFF + Z_F)                 // weights [18][32]
#define SW_F    (18 * CHO)                    // 576
#define SMEM_BYTES ((SW_OFF + SW_F) * 4)      // 101376 B

// packed f32x2 fma: d = a*b + d
__device__ __forceinline__ void fma2(unsigned long long &d,
                                     unsigned long long a,
                                     unsigned long long b) {
    asm("fma.rn.f32x2 %0, %1, %2, %3;" : "=l"(d) : "l"(a), "l"(b), "l"(d));
}

__global__ __launch_bounds__(NTHR, 2)
void snn_encoder_kernel(const float* __restrict__ spike,
                        const float* __restrict__ weight_v,
                        const float* __restrict__ weight_g,
                        const float* __restrict__ delay,
                        float* __restrict__ out) {
    extern __shared__ __align__(16) float smem[];
    float* sin_ = smem;              // [plane(6)][w(33)][t(32)]
    float* zbuf = smem + Z_OFF;      // [(ch*16+wp)][36]
    float* sw   = smem + SW_OFF;     // [tap(18)][ch(32)]

    const int tid  = threadIdx.x;
    const int lane = tid & 31;
    const int wid  = tid >> 5;       // warp 0..15: channels 2*wid, 2*wid+1
    const int tp   = lane & 15;      // t-pair index: t = 2*tp, 2*tp+1
    const int half = lane >> 4;      // wp parity within a wp-pair iteration
    const int wp0  = blockIdx.x * WPT;
    const int hp   = blockIdx.y;
    const int n    = blockIdx.z;

    // ---- weight norm (one thread per output channel) ----
    if (tid < 32) {
        float wv[18];
        float ss = 0.f;
        #pragma unroll
        for (int k = 0; k < 18; k++) {
            wv[k] = weight_v[tid * 18 + k];
            ss += wv[k] * wv[k];
        }
        const float sc = weight_g[tid] / sqrtf(ss);
        #pragma unroll
        for (int k = 0; k < 18; k++)
            sw[k * 32 + tid] = wv[k] * sc;
    }

    // ---- cooperative input tile load (coalesced; (w,t) contiguous) ----
    const int h0 = 2 * hp - 1;
    const int w0 = 2 * wp0 - 1;
    for (int idx = tid; idx < CIN * 3 * TILE_W * 8; idx += NTHR) {
        const int plane = idx / (TILE_W * 8);        // c*3 + r
        const int rem   = idx - plane * (TILE_W * 8);
        const int wj    = rem >> 3;
        const int t4    = rem & 7;
        const int c = plane / 3;
        const int r = plane - c * 3;
        const int h = h0 + r;
        const int w = w0 + wj;
        float4 v = make_float4(0.f, 0.f, 0.f, 0.f);
        if ((unsigned)h < HIN && (unsigned)w < WIN) {
            v = *(const float4*)(spike +
                (((size_t)(n * CIN + c) * HIN + h) * WIN + w) * TT + t4 * 4);
        }
        *(float4*)(sin_ + (plane * TILE_W + wj) * TT + t4 * 4) = v;
    }
    __syncthreads();

    // ---- PHASE 1: conv, weight-stationary. warp = 2 ch, lane = (tp, half) ----
    // 36 weight regs (f32x2-dup'd), 4 accumulator regs: fits 64-reg cap, no spill.
    {
        unsigned long long wdup[18][2];
        #pragma unroll
        for (int k = 0; k < 18; k++) {
            const float2 wv2 = *(const float2*)(sw + k * 32 + 2 * wid);
            const unsigned int u0 = __float_as_uint(wv2.x);
            const unsigned int u1 = __float_as_uint(wv2.y);
            wdup[k][0] = ((unsigned long long)u0 << 32) | u0;
            wdup[k][1] = ((unsigned long long)u1 << 32) | u1;
        }
        const float* tbase = sin_ + 2 * tp;
        #pragma unroll 2
        for (int wpi = 0; wpi < WPT / 2; wpi++) {
            const int wp = 2 * wpi + half;
            unsigned long long za = 0ull, zb = 0ull;   // {t,t+1} for ch0, ch1
            #pragma unroll
            for (int c = 0; c < CIN; c++) {
                #pragma unroll
                for (int r = 0; r < 3; r++) {
                    #pragma unroll
                    for (int kw = 0; kw < 3; kw++) {
                        const int k = c * 9 + r * 3 + kw;
                        const unsigned long long a = *(const unsigned long long*)(
                            tbase + ((c * 3 + r) * TILE_W + 2 * wp + kw) * TT);
                        fma2(za, a, wdup[k][0]);
                        fma2(zb, a, wdup[k][1]);
                    }
                }
            }
            float* zr0 = zbuf + ((2 * wid)     * WPT + wp) * ZROW + 2 * tp;
            float* zr1 = zbuf + ((2 * wid + 1) * WPT + wp) * ZROW + 2 * tp;
            *(unsigned long long*)zr0 = za;
            *(unsigned long long*)zr1 = zb;
        }
    }
    __syncthreads();

    // ---- PHASE 2: LIF scan, t-in-thread; one (ch,wp) row per thread ----
    unsigned int* sb = (unsigned int*)sin_;   // sbits[ch*16+wp], aliases dead tile
    {
        const float* zr = zbuf + tid * ZROW;
        float cur = 0.f, volt = 0.f;
        unsigned int bits = 0u;
        #pragma unroll
        for (int q = 0; q < 8; q++) {
            const float4 z4 = *(const float4*)(zr + q * 4);
            const int t = q * 4;
            cur  = cur * 0.75f + z4.x;
            volt = volt * 0.9f + cur;
            { const bool s = volt >= 1.0f; bits |= s ? (1u << t) : 0u; volt = s ? 0.f : volt; }
            cur  = cur * 0.75f + z4.y;
            volt = volt * 0.9f + cur;
            { const bool s = volt >= 1.0f; bits |= s ? (1u << (t+1)) : 0u; volt = s ? 0.f : volt; }
            cur  = cur * 0.75f + z4.z;
            volt = volt * 0.9f + cur;
            { const bool s = volt >= 1.0f; bits |= s ? (1u << (t+2)) : 0u; volt = s ? 0.f : volt; }
            cur  = cur * 0.75f + z4.w;
            volt = volt * 0.9f + cur;
            { const bool s = volt >= 1.0f; bits |= s ? (1u << (t+3)) : 0u; volt = s ? 0.f : volt; }
        }
        sb[tid] = bits;
    }
    __syncthreads();

    // ---- PHASE 3: coalesced epilogue. warp wid writes ch wid and wid+16 ----
    #pragma unroll
    for (int sp = 0; sp < 2; sp++) {
        const int ch = wid + 16 * sp;
        const float d  = delay[ch];           // warp-uniform
        const int   di = (int)floorf(d);
        const float f  = d - (float)di;
        const float onef = 1.0f - f;
        float* obase = out +
            (((size_t)((n * CHO + ch) * HP + hp) * WPX + wp0) * TT);
        #pragma unroll
        for (int i = 0; i < 4; i++) {
            const int idx = i * 32 + lane;    // 0..127 float4 slots (16wp x 8)
            const int wpi = idx >> 3;
            const int t   = (idx & 7) * 4;
            const unsigned int bt = sb[ch * WPT + wpi];
            unsigned int b0 = 0u, b1 = 0u;
            if (di >= 0 && di < 32)         b0 = bt << di;
            if (di + 1 >= 0 && di + 1 < 32) b1 = bt << (di + 1);
            float4 v;
            v.x = onef * (float)((b0 >> (t + 0)) & 1u) + f * (float)((b1 >> (t + 0)) & 1u);
            v.y = onef * (float)((b0 >> (t + 1)) & 1u) + f * (float)((b1 >> (t + 1)) & 1u);
            v.z = onef * (float)((b0 >> (t + 2)) & 1u) + f * (float)((b1 >> (t + 2)) & 1u);
            v.w = onef * (float)((b0 >> (t + 3)) & 1u) + f * (float)((b1 >> (t + 3)) & 1u);
            *(float4*)(obase + idx * 4) = v;
        }
    }
}

extern "C" void kernel_launch(void* const* d_in, const int* in_sizes, int n_in,
                              void* d_out, int out_size) {
    const float* spike    = (const float*)d_in[0];
    const float* weight_v = (const float*)d_in[1];
    const float* weight_g = (const float*)d_in[2];
    const float* delay    = (const float*)d_in[3];
    float* out = (float*)d_out;

    cudaFuncSetAttribute(snn_encoder_kernel,
                         cudaFuncAttributeMaxDynamicSharedMemorySize, SMEM_BYTES);
    dim3 grid(WPX / WPT, HP, NB);   // (4, 64, 8) = 2048 blocks
    snn_encoder_kernel<<<grid, NTHR, SMEM_BYTES>>>(spike, weight_v, weight_g, delay, out);
}

// round 10
// speedup vs baseline: 2.3174x; 1.0357x over previous
#include <cuda_runtime.h>

// Problem constants
#define NB     8
#define CIN    2
#define HIN    128
#define WIN    128
#define TT     32
#define CHO    32
#define HP     64
#define WPX    64
#define WPT    16            // wp columns per block
#define NTHR   512           // 16 warps: warp = 4 ch x 8 wp, lane = t
#define TILE_W 33            // 2*WPT + 1 halo

// smem layout (floats)
#define TILE_F  (CIN * 3 * TILE_W * TT)      // 6336  : input tile [6][33][32]
#define ZROW    36                            // padded t-row: 144 B (16B-aligned rows)
#define Z_OFF   TILE_F                        // z[32ch*16wp][36]
#define Z_F     (CHO * WPT * ZROW)            // 18432
#define SW_OFF  (Z_OFF + Z_F)                 // weights [18][32]
#define SW_F    (18 * CHO)                    // 576
#define SB_OFF  (SW_OFF + SW_F)               // spike bitmasks [512] (own region:
                                              // phase 2 may run while others conv)
#define SMEM_BYTES ((SB_OFF + 512) * 4)       // 103424 B ; x2 blocks = 206848 fits

#define CHROW   (WPT * ZROW)                  // 576 floats between adjacent ch rows

// packed f32x2 fma: d = a*b + d
__device__ __forceinline__ void fma2(unsigned long long &d,
                                     unsigned long long a,
                                     unsigned long long b) {
    asm("fma.rn.f32x2 %0, %1, %2, %3;" : "=l"(d) : "l"(a), "l"(b), "l"(d));
}
// pack two floats into an f32x2 register pair {lo, hi}
__device__ __forceinline__ unsigned long long pk2(float lo, float hi) {
    unsigned long long r;
    asm("mov.b64 %0, {%1, %2};" : "=l"(r)
        : "r"(__float_as_uint(lo)), "r"(__float_as_uint(hi)));
    return r;
}
__device__ __forceinline__ float f2lo(unsigned long long v) {
    return __uint_as_float((unsigned)(v & 0xffffffffull));
}
__device__ __forceinline__ float f2hi(unsigned long long v) {
    return __uint_as_float((unsigned)(v >> 32));
}

__global__ __launch_bounds__(NTHR, 2)
void snn_encoder_kernel(const float* __restrict__ spike,
                        const float* __restrict__ weight_v,
                        const float* __restrict__ weight_g,
                        const float* __restrict__ delay,
                        float* __restrict__ out) {
    extern __shared__ __align__(16) float smem[];
    float* sin_ = smem;              // [plane(6)][w(33)][t(32)]
    float* zbuf = smem + Z_OFF;      // [(ch*16+wp)][36]
    float* sw   = smem + SW_OFF;     // [tap(18)][ch(32)]
    unsigned int* sb = (unsigned int*)(smem + SB_OFF);   // sbits[512]

    const int tid  = threadIdx.x;
    const int lane = tid & 31;       // phase 1: lane = t
    const int wid  = tid >> 5;       // warp 0..15
    const int cg   = wid & 7;        // channel group: ch 4*cg .. 4*cg+3
    const int wh   = wid >> 3;       // wp half: wp = 8*wh + j
    const int wp0  = blockIdx.x * WPT;
    const int hp   = blockIdx.y;
    const int n    = blockIdx.z;

    // ---- weight norm (one thread per output channel) ----
    if (tid < 32) {
        float wv[18];
        float ss = 0.f;
        #pragma unroll
        for (int k = 0; k < 18; k++) {
            wv[k] = weight_v[tid * 18 + k];
            ss += wv[k] * wv[k];
        }
        const float sc = weight_g[tid] / sqrtf(ss);
        #pragma unroll
        for (int k = 0; k < 18; k++)
            sw[k * 32 + tid] = wv[k] * sc;
    }

    // ---- cooperative input tile load (coalesced; (w,t) contiguous) ----
    const int h0 = 2 * hp - 1;
    const int w0 = 2 * wp0 - 1;
    for (int idx = tid; idx < CIN * 3 * TILE_W * 8; idx += NTHR) {
        const int plane = idx / (TILE_W * 8);        // c*3 + r
        const int rem   = idx - plane * (TILE_W * 8);
        const int wj    = rem >> 3;
        const int t4    = rem & 7;
        const int c = plane / 3;
        const int r = plane - c * 3;
        const int h = h0 + r;
        const int w = w0 + wj;
        float4 v = make_float4(0.f, 0.f, 0.f, 0.f);
        if ((unsigned)h < HIN && (unsigned)w < WIN) {
            v = *(const float4*)(spike +
                (((size_t)(n * CIN + c) * HIN + h) * WIN + w) * TT + t4 * 4);
        }
        *(float4*)(sin_ + (plane * TILE_W + wj) * TT + t4 * 4) = v;
    }
    __syncthreads();

    // ---- PHASE 1: conv. warp = 4 ch x 8 wp, lane = t.
    // Channel-packed f32x2 weights + duplicated taps; two 9-tap passes over
    // input channel c keep weight regs at 36 (fits 64-reg cap, 50% occ).
    // Pass 2 initializes accumulators from pass-1 partials -> summation order
    // k=0..17 is bit-identical to previous rounds.
    {   // pass c = 0
        unsigned long long w01[9], w23[9];
        #pragma unroll
        for (int k = 0; k < 9; k++) {
            const float4 wv = *(const float4*)(sw + k * 32 + 4 * cg);
            w01[k] = pk2(wv.x, wv.y);
            w23[k] = pk2(wv.z, wv.w);
        }
        #pragma unroll 2
        for (int j = 0; j < 8; j++) {
            const int wp = 8 * wh + j;
            unsigned long long a01 = 0ull, a23 = 0ull;
            #pragma unroll
            for (int r = 0; r < 3; r++) {
                #pragma unroll
                for (int kw = 0; kw < 3; kw++) {
                    const int k = r * 3 + kw;
                    const float tap = sin_[(r * TILE_W + 2 * wp + kw) * TT + lane];
                    const unsigned long long t2 = pk2(tap, tap);
                    fma2(a01, t2, w01[k]);
                    fma2(a23, t2, w23[k]);
                }
            }
            float* zr = zbuf + ((4 * cg) * WPT + wp) * ZROW + lane;
            zr[0 * CHROW] = f2lo(a01);
            zr[1 * CHROW] = f2hi(a01);
            zr[2 * CHROW] = f2lo(a23);
            zr[3 * CHROW] = f2hi(a23);
        }
    }
    {   // pass c = 1 (accumulate onto partials, exact sequential order)
        unsigned long long w01[9], w23[9];
        #pragma unroll
        for (int k = 0; k < 9; k++) {
            const float4 wv = *(const float4*)(sw + (9 + k) * 32 + 4 * cg);
            w01[k] = pk2(wv.x, wv.y);
            w23[k] = pk2(wv.z, wv.w);
        }
        #pragma unroll 2
        for (int j = 0; j < 8; j++) {
            const int wp = 8 * wh + j;
            float* zr = zbuf + ((4 * cg) * WPT + wp) * ZROW + lane;
            unsigned long long a01 = pk2(zr[0 * CHROW], zr[1 * CHROW]);
            unsigned long long a23 = pk2(zr[2 * CHROW], zr[3 * CHROW]);
            #pragma unroll
            for (int r = 0; r < 3; r++) {
                #pragma unroll
                for (int kw = 0; kw < 3; kw++) {
                    const int k = r * 3 + kw;
                    const float tap = sin_[((3 + r) * TILE_W + 2 * wp + kw) * TT + lane];
                    const unsigned long long t2 = pk2(tap, tap);
                    fma2(a01, t2, w01[k]);
                    fma2(a23, t2, w23[k]);
                }
            }
            zr[0 * CHROW] = f2lo(a01);
            zr[1 * CHROW] = f2hi(a01);
            zr[2 * CHROW] = f2lo(a23);
            zr[3 * CHROW] = f2hi(a23);
        }
    }
    __syncwarp();   // z rows below are warp-private: no block barrier needed

    // ---- PHASE 2: LIF scan. lane -> one of this warp's own 32 (ch,wp) rows ----
    {
        const int row = (4 * cg + (lane >> 3)) * WPT + 8 * wh + (lane & 7);
        const float* zr = zbuf + row * ZROW;
        float cur = 0.f, volt = 0.f;
        unsigned int bits = 0u;
        #pragma unroll
        for (int q = 0; q < 8; q++) {
            const float4 z4 = *(const float4*)(zr + q * 4);
            const int t = q * 4;
            cur  = cur * 0.75f + z4.x;
            volt = volt * 0.9f + cur;
            { const bool s = volt >= 1.0f; bits |= s ? (1u << t) : 0u; volt = s ? 0.f : volt; }
            cur  = cur * 0.75f + z4.y;
            volt = volt * 0.9f + cur;
            { const bool s = volt >= 1.0f; bits |= s ? (1u << (t+1)) : 0u; volt = s ? 0.f : volt; }
            cur  = cur * 0.75f + z4.z;
            volt = volt * 0.9f + cur;
            { const bool s = volt >= 1.0f; bits |= s ? (1u << (t+2)) : 0u; volt = s ? 0.f : volt; }
            cur  = cur * 0.75f + z4.w;
            volt = volt * 0.9f + cur;
            { const bool s = volt >= 1.0f; bits |= s ? (1u << (t+3)) : 0u; volt = s ? 0.f : volt; }
        }
        sb[row] = bits;
    }
    __syncthreads();

    // ---- PHASE 3: coalesced epilogue. warp wid writes ch wid and wid+16 ----
    #pragma unroll
    for (int sp = 0; sp < 2; sp++) {
        const int ch = wid + 16 * sp;
        const float d  = delay[ch];           // warp-uniform
        const int   di = (int)floorf(d);
        const float f  = d - (float)di;
        const float onef = 1.0f - f;
        float* obase = out +
            (((size_t)((n * CHO + ch) * HP + hp) * WPX + wp0) * TT);
        #pragma unroll
        for (int i = 0; i < 4; i++) {
            const int idx = i * 32 + lane;    // 0..127 float4 slots (16wp x 8)
            const int wpi = idx >> 3;
            const int t   = (idx & 7) * 4;
            const unsigned int bt = sb[ch * WPT + wpi];
            unsigned int b0 = 0u, b1 = 0u;
            if (di >= 0 && di < 32)         b0 = bt << di;
            if (di + 1 >= 0 && di + 1 < 32) b1 = bt << (di + 1);
            float4 v;
            v.x = onef * (float)((b0 >> (t + 0)) & 1u) + f * (float)((b1 >> (t + 0)) & 1u);
            v.y = onef * (float)((b0 >> (t + 1)) & 1u) + f * (float)((b1 >> (t + 1)) & 1u);
            v.z = onef * (float)((b0 >> (t + 2)) & 1u) + f * (float)((b1 >> (t + 2)) & 1u);
            v.w = onef * (float)((b0 >> (t + 3)) & 1u) + f * (float)((b1 >> (t + 3)) & 1u);
            *(float4*)(obase + idx * 4) = v;
        }
    }
}

extern "C" void kernel_launch(void* const* d_in, const int* in_sizes, int n_in,
                              void* d_out, int out_size) {
    const float* spike    = (const float*)d_in[0];
    const float* weight_v = (const float*)d_in[1];
    const float* weight_g = (const float*)d_in[2];
    const float* delay    = (const float*)d_in[3];
    float* out = (float*)d_out;

    cudaFuncSetAttribute(snn_encoder_kernel,
                         cudaFuncAttributeMaxDynamicSharedMemorySize, SMEM_BYTES);
    dim3 grid(WPX / WPT, HP, NB);   // (4, 64, 8) = 2048 blocks
    snn_encoder_kernel<<<grid, NTHR, SMEM_BYTES>>>(spike, weight_v, weight_g, delay, out);
}

// round 11
// speedup vs baseline: 2.3262x; 1.0038x over previous
#include <cuda_runtime.h>

// Problem constants
#define NB     8
#define CIN    2
#define HIN    128
#define WIN    128
#define TT     32
#define CHO    32
#define HP     64
#define WPX    64
#define WPT    16            // wp columns per block
#define NTHR   512           // 16 warps: warp = 4 ch x 8 wp, lane = t
#define TILE_W 33            // 2*WPT + 1 halo

// smem layout (floats)
#define TILE_F  (CIN * 3 * TILE_W * TT)      // 6336  : input tile [6][33][32]
#define ZROW    36                            // padded t-row: 144 B (16B-aligned rows)
#define Z_OFF   TILE_F                        // z[32ch*16wp][36]
#define Z_F     (CHO * WPT * ZROW)            // 18432
#define SW_OFF  (Z_OFF + Z_F)                 // weights [18][32]
#define SW_F    (18 * CHO)                    // 576
#define SB_OFF  (SW_OFF + SW_F)               // spike bitmasks [512]
#define SMEM_BYTES ((SB_OFF + 512) * 4)       // 103424 B ; x2 blocks fits 227KB

#define CHROW   (WPT * ZROW)                  // 576 floats between adjacent ch rows

// packed f32x2 fma: d = a*b + d
__device__ __forceinline__ void fma2(unsigned long long &d,
                                     unsigned long long a,
                                     unsigned long long b) {
    asm("fma.rn.f32x2 %0, %1, %2, %3;" : "=l"(d) : "l"(a), "l"(b), "l"(d));
}
// pack two floats into an f32x2 register pair {lo, hi}
__device__ __forceinline__ unsigned long long pk2(float lo, float hi) {
    unsigned long long r;
    asm("mov.b64 %0, {%1, %2};" : "=l"(r)
        : "r"(__float_as_uint(lo)), "r"(__float_as_uint(hi)));
    return r;
}
__device__ __forceinline__ float f2lo(unsigned long long v) {
    return __uint_as_float((unsigned)(v & 0xffffffffull));
}
__device__ __forceinline__ float f2hi(unsigned long long v) {
    return __uint_as_float((unsigned)(v >> 32));
}

__global__ __launch_bounds__(NTHR, 2)
void snn_encoder_kernel(const float* __restrict__ spike,
                        const float* __restrict__ weight_v,
                        const float* __restrict__ weight_g,
                        const float* __restrict__ delay,
                        float* __restrict__ out) {
    extern __shared__ __align__(16) float smem[];
    float* sin_ = smem;              // [plane(6)][w(33)][t(32)]
    float* zbuf = smem + Z_OFF;      // [(ch*16+wp)][36]
    float* sw   = smem + SW_OFF;     // [tap(18)][ch(32)]
    unsigned int* sb = (unsigned int*)(smem + SB_OFF);   // sbits[512]

    const int tid  = threadIdx.x;
    const int lane = tid & 31;       // phase 1: lane = t
    const int wid  = tid >> 5;       // warp 0..15
    const int cg   = wid & 7;        // channel group: ch 4*cg .. 4*cg+3
    const int wh   = wid >> 3;       // wp half: wp = 8*wh + j
    const int wp0  = blockIdx.x * WPT;
    const int hp   = blockIdx.y;
    const int n    = blockIdx.z;

    // ---- weight norm (one thread per output channel) ----
    if (tid < 32) {
        float wv[18];
        float ss = 0.f;
        #pragma unroll
        for (int k = 0; k < 18; k++) {
            wv[k] = weight_v[tid * 18 + k];
            ss += wv[k] * wv[k];
        }
        const float sc = weight_g[tid] / sqrtf(ss);
        #pragma unroll
        for (int k = 0; k < 18; k++)
            sw[k * 32 + tid] = wv[k] * sc;
    }

    // ---- cooperative input tile load (coalesced; (w,t) contiguous) ----
    const int h0 = 2 * hp - 1;
    const int w0 = 2 * wp0 - 1;
    for (int idx = tid; idx < CIN * 3 * TILE_W * 8; idx += NTHR) {
        const int plane = idx / (TILE_W * 8);        // c*3 + r
        const int rem   = idx - plane * (TILE_W * 8);
        const int wj    = rem >> 3;
        const int t4    = rem & 7;
        const int c = plane / 3;
        const int r = plane - c * 3;
        const int h = h0 + r;
        const int w = w0 + wj;
        float4 v = make_float4(0.f, 0.f, 0.f, 0.f);
        if ((unsigned)h < HIN && (unsigned)w < WIN) {
            v = *(const float4*)(spike +
                (((size_t)(n * CIN + c) * HIN + h) * WIN + w) * TT + t4 * 4);
        }
        *(float4*)(sin_ + (plane * TILE_W + wj) * TT + t4 * 4) = v;
    }
    __syncthreads();

    // ---- PHASE 1: conv. warp = 4 ch x 8 wp, lane = t.
    // Channel-packed f32x2 weights; two 9-tap passes over input channel c.
    // kw-rolling: output col wp's kw=2 tap == (wp+1)'s kw=0 tap -> reuse the
    // dup'd register, saving 1/3 of tap LDS + pk2 movs. Same loads, same fma
    // order k=0..8 per accumulator -> z bit-identical to round 10.
    #pragma unroll 1
    for (int cpass = 0; cpass < CIN; cpass++) {
        unsigned long long w01[9], w23[9];
        #pragma unroll
        for (int k = 0; k < 9; k++) {
            const float4 wv = *(const float4*)(sw + (9 * cpass + k) * 32 + 4 * cg);
            w01[k] = pk2(wv.x, wv.y);
            w23[k] = pk2(wv.z, wv.w);
        }
        const float* pl0 = sin_ + (3 * cpass + 0) * TILE_W * TT + lane;
        const float* pl1 = sin_ + (3 * cpass + 1) * TILE_W * TT + lane;
        const float* pl2 = sin_ + (3 * cpass + 2) * TILE_W * TT + lane;
        const int wpb = 8 * wh;
        // rolling kw=0 taps (dup'd) for r = 0,1,2
        float s0 = pl0[(2 * wpb) * TT];
        float s1 = pl1[(2 * wpb) * TT];
        float s2 = pl2[(2 * wpb) * TT];
        unsigned long long tr0 = pk2(s0, s0);
        unsigned long long tr1 = pk2(s1, s1);
        unsigned long long tr2 = pk2(s2, s2);
        #pragma unroll
        for (int j = 0; j < 8; j++) {
            const int wp = wpb + j;
            const int col = 2 * wp;
            float* zr = zbuf + ((4 * cg) * WPT + wp) * ZROW + lane;
            unsigned long long a01, a23;
            if (cpass == 0) { a01 = 0ull; a23 = 0ull; }
            else {
                a01 = pk2(zr[0 * CHROW], zr[1 * CHROW]);
                a23 = pk2(zr[2 * CHROW], zr[3 * CHROW]);
            }
            // r = 0
            {
                const float tb = pl0[(col + 1) * TT];
                const float tc = pl0[(col + 2) * TT];
                const unsigned long long t1 = pk2(tb, tb);
                const unsigned long long t2 = pk2(tc, tc);
                fma2(a01, tr0, w01[0]);  fma2(a23, tr0, w23[0]);
                fma2(a01, t1,  w01[1]);  fma2(a23, t1,  w23[1]);
                fma2(a01, t2,  w01[2]);  fma2(a23, t2,  w23[2]);
                tr0 = t2;
            }
            // r = 1
            {
                const float tb = pl1[(col + 1) * TT];
                const float tc = pl1[(col + 2) * TT];
                const unsigned long long t1 = pk2(tb, tb);
                const unsigned long long t2 = pk2(tc, tc);
                fma2(a01, tr1, w01[3]);  fma2(a23, tr1, w23[3]);
                fma2(a01, t1,  w01[4]);  fma2(a23, t1,  w23[4]);
                fma2(a01, t2,  w01[5]);  fma2(a23, t2,  w23[5]);
                tr1 = t2;
            }
            // r = 2
            {
                const float tb = pl2[(col + 1) * TT];
                const float tc = pl2[(col + 2) * TT];
                const unsigned long long t1 = pk2(tb, tb);
                const unsigned long long t2 = pk2(tc, tc);
                fma2(a01, tr2, w01[6]);  fma2(a23, tr2, w23[6]);
                fma2(a01, t1,  w01[7]);  fma2(a23, t1,  w23[7]);
                fma2(a01, t2,  w01[8]);  fma2(a23, t2,  w23[8]);
                tr2 = t2;
            }
            zr[0 * CHROW] = f2lo(a01);
            zr[1 * CHROW] = f2hi(a01);
            zr[2 * CHROW] = f2lo(a23);
            zr[3 * CHROW] = f2hi(a23);
        }
    }
    __syncwarp();   // z rows below are warp-private

    // ---- PHASE 2: LIF scan. lane -> one of this warp's own 32 (ch,wp) rows ----
    {
        const int row = (4 * cg + (lane >> 3)) * WPT + 8 * wh + (lane & 7);
        const float* zr = zbuf + row * ZROW;
        float cur = 0.f, volt = 0.f;
        unsigned int bits = 0u;
        #pragma unroll
        for (int q = 0; q < 8; q++) {
            const float4 z4 = *(const float4*)(zr + q * 4);
            const int t = q * 4;
            cur  = cur * 0.75f + z4.x;
            volt = volt * 0.9f + cur;
            { const bool s = volt >= 1.0f; bits |= s ? (1u << t) : 0u; volt = s ? 0.f : volt; }
            cur  = cur * 0.75f + z4.y;
            volt = volt * 0.9f + cur;
            { const bool s = volt >= 1.0f; bits |= s ? (1u << (t+1)) : 0u; volt = s ? 0.f : volt; }
            cur  = cur * 0.75f + z4.z;
            volt = volt * 0.9f + cur;
            { const bool s = volt >= 1.0f; bits |= s ? (1u << (t+2)) : 0u; volt = s ? 0.f : volt; }
            cur  = cur * 0.75f + z4.w;
            volt = volt * 0.9f + cur;
            { const bool s = volt >= 1.0f; bits |= s ? (1u << (t+3)) : 0u; volt = s ? 0.f : volt; }
        }
        sb[row] = bits;
    }
    __syncthreads();

    // ---- PHASE 3: coalesced epilogue. warp wid writes ch wid and wid+16 ----
    #pragma unroll
    for (int sp = 0; sp < 2; sp++) {
        const int ch = wid + 16 * sp;
        const float d  = delay[ch];           // warp-uniform
        const int   di = (int)floorf(d);
        const float f  = d - (float)di;
        const float onef = 1.0f - f;
        float* obase = out +
            (((size_t)((n * CHO + ch) * HP + hp) * WPX + wp0) * TT);
        #pragma unroll
        for (int i = 0; i < 4; i++) {
            const int idx = i * 32 + lane;    // 0..127 float4 slots (16wp x 8)
            const int wpi = idx >> 3;
            const int t   = (idx & 7) * 4;
            const unsigned int bt = sb[ch * WPT + wpi];
            unsigned int b0 = 0u, b1 = 0u;
            if (di >= 0 && di < 32)         b0 = bt << di;
            if (di + 1 >= 0 && di + 1 < 32) b1 = bt << (di + 1);
            float4 v;
            v.x = (((b0 >> (t + 0)) & 1u) ? onef : 0.f) + (((b1 >> (t + 0)) & 1u) ? f : 0.f);
            v.y = (((b0 >> (t + 1)) & 1u) ? onef : 0.f) + (((b1 >> (t + 1)) & 1u) ? f : 0.f);
            v.z = (((b0 >> (t + 2)) & 1u) ? onef : 0.f) + (((b1 >> (t + 2)) & 1u) ? f : 0.f);
            v.w = (((b0 >> (t + 3)) & 1u) ? onef : 0.f) + (((b1 >> (t + 3)) & 1u) ? f : 0.f);
            *(float4*)(obase + idx * 4) = v;
        }
    }
}

extern "C" void kernel_launch(void* const* d_in, const int* in_sizes, int n_in,
                              void* d_out, int out_size) {
    const float* spike    = (const float*)d_in[0];
    const float* weight_v = (const float*)d_in[1];
    const float* weight_g = (const float*)d_in[2];
    const float* delay    = (const float*)d_in[3];
    float* out = (float*)d_out;

    cudaFuncSetAttribute(snn_encoder_kernel,
                         cudaFuncAttributeMaxDynamicSharedMemorySize, SMEM_BYTES);
    dim3 grid(WPX / WPT, HP, NB);   // (4, 64, 8) = 2048 blocks
    snn_encoder_kernel<<<grid, NTHR, SMEM_BYTES>>>(spike, weight_v, weight_g, delay, out);
}

// round 12
// speedup vs baseline: 2.7614x; 1.1871x over previous
#include <cuda_runtime.h>

// Problem constants
#define NB     8
#define CIN    2
#define HIN    128
#define WIN    128
#define TT     32
#define CHO    32
#define HP     64
#define WPX    64
#define WPT    8             // wp columns per block
#define NTHR   256           // 8 warps: warp = 4 ch x 8 wp, lane = t
#define TILE_W 17            // 2*WPT + 1 halo

// smem layout (floats)
#define TILE_F  (CIN * 3 * TILE_W * TT)      // 3264 : input tile [6][17][32]
#define ZBLK    132                           // per-(cg,wp) z block: [t(32)][ch(4)]+pad
                                              // 132 mod 32 = 4 -> 4-bank rotation:
                                              // conflict-free STS.128 and phase-2 reads
#define Z_OFF   TILE_F
#define Z_F     (8 * WPT * ZBLK)              // 8448
#define SW_OFF  (Z_OFF + Z_F)                 // weights [18][32]
#define SW_F    (18 * CHO)                    // 576
#define SB_OFF  (SW_OFF + SW_F)               // spike bitmasks [256]
#define SMEM_BYTES ((SB_OFF + 256) * 4)       // 50176 B ; x4 blocks = 200704 fits

// packed f32x2 fma: d = a*b + d
__device__ __forceinline__ void fma2(unsigned long long &d,
                                     unsigned long long a,
                                     unsigned long long b) {
    asm("fma.rn.f32x2 %0, %1, %2, %3;" : "=l"(d) : "l"(a), "l"(b), "l"(d));
}
// pack two floats into an f32x2 register pair {lo, hi}
__device__ __forceinline__ unsigned long long pk2(float lo, float hi) {
    unsigned long long r;
    asm("mov.b64 %0, {%1, %2};" : "=l"(r)
        : "r"(__float_as_uint(lo)), "r"(__float_as_uint(hi)));
    return r;
}
__device__ __forceinline__ float f2lo(unsigned long long v) {
    return __uint_as_float((unsigned)(v & 0xffffffffull));
}
__device__ __forceinline__ float f2hi(unsigned long long v) {
    return __uint_as_float((unsigned)(v >> 32));
}

__global__ __launch_bounds__(NTHR, 4)
void snn_encoder_kernel(const float* __restrict__ spike,
                        const float* __restrict__ weight_v,
                        const float* __restrict__ weight_g,
                        const float* __restrict__ delay,
                        float* __restrict__ out) {
    extern __shared__ __align__(16) float smem[];
    float* sin_ = smem;              // [plane(6)][w(17)][t(32)]
    float* zbuf = smem + Z_OFF;      // [(cg*8+wp)][132] = [t*4 + c]
    float* sw   = smem + SW_OFF;     // [tap(18)][ch(32)]
    unsigned int* sb = (unsigned int*)(smem + SB_OFF);   // sbits[256]

    const int tid  = threadIdx.x;
    const int lane = tid & 31;       // phase 1: lane = t
    const int cg   = tid >> 5;       // warp 0..7: channels 4*cg .. 4*cg+3
    const int wp0  = blockIdx.x * WPT;
    const int hp   = blockIdx.y;
    const int n    = blockIdx.z;

    // ---- weight norm (one thread per output channel) ----
    if (tid < 32) {
        float wv[18];
        float ss = 0.f;
        #pragma unroll
        for (int k = 0; k < 18; k++) {
            wv[k] = weight_v[tid * 18 + k];
            ss += wv[k] * wv[k];
        }
        const float sc = weight_g[tid] / sqrtf(ss);
        #pragma unroll
        for (int k = 0; k < 18; k++)
            sw[k * 32 + tid] = wv[k] * sc;
    }

    // ---- cooperative input tile load (coalesced; (w,t) contiguous) ----
    const int h0 = 2 * hp - 1;
    const int w0 = 2 * wp0 - 1;
    for (int idx = tid; idx < CIN * 3 * TILE_W * 8; idx += NTHR) {
        const int plane = idx / (TILE_W * 8);        // c*3 + r
        const int rem   = idx - plane * (TILE_W * 8);
        const int wj    = rem >> 3;
        const int t4    = rem & 7;
        const int c = plane / 3;
        const int r = plane - c * 3;
        const int h = h0 + r;
        const int w = w0 + wj;
        float4 v = make_float4(0.f, 0.f, 0.f, 0.f);
        if ((unsigned)h < HIN && (unsigned)w < WIN) {
            v = *(const float4*)(spike +
                (((size_t)(n * CIN + c) * HIN + h) * WIN + w) * TT + t4 * 4);
        }
        *(float4*)(sin_ + (plane * TILE_W + wj) * TT + t4 * 4) = v;
    }
    __syncthreads();

    // ---- PHASE 1: conv. warp = 4 ch x 8 wp, lane = t.
    // Two 9-tap passes over input channel c (36 weight regs each; fits 64-reg
    // cap). kw-rolling tap reuse. z stored channel-interleaved: one STS.128
    // per (j, pass); pass 2 does LDS.128 + STS.128. Summation order k=0..17
    // per accumulator unchanged -> z bit-identical to round 11.
    #pragma unroll 1
    for (int cpass = 0; cpass < CIN; cpass++) {
        unsigned long long w01[9], w23[9];
        #pragma unroll
        for (int k = 0; k < 9; k++) {
            const float4 wv = *(const float4*)(sw + (9 * cpass + k) * 32 + 4 * cg);
            w01[k] = pk2(wv.x, wv.y);
            w23[k] = pk2(wv.z, wv.w);
        }
        const float* pl0 = sin_ + (3 * cpass + 0) * TILE_W * TT + lane;
        const float* pl1 = sin_ + (3 * cpass + 1) * TILE_W * TT + lane;
        const float* pl2 = sin_ + (3 * cpass + 2) * TILE_W * TT + lane;
        // rolling kw=0 taps (dup'd) for r = 0,1,2
        float s0 = pl0[0];
        float s1 = pl1[0];
        float s2 = pl2[0];
        unsigned long long tr0 = pk2(s0, s0);
        unsigned long long tr1 = pk2(s1, s1);
        unsigned long long tr2 = pk2(s2, s2);
        #pragma unroll
        for (int j = 0; j < 8; j++) {
            const int col = 2 * j;
            float* zr = zbuf + (cg * WPT + j) * ZBLK + 4 * lane;
            unsigned long long a01, a23;
            if (cpass == 0) { a01 = 0ull; a23 = 0ull; }
            else {
                const float4 zp = *(const float4*)zr;
                a01 = pk2(zp.x, zp.y);
                a23 = pk2(zp.z, zp.w);
            }
            // r = 0
            {
                const float tb = pl0[(col + 1) * TT];
                const float tc = pl0[(col + 2) * TT];
                const unsigned long long t1 = pk2(tb, tb);
                const unsigned long long t2 = pk2(tc, tc);
                fma2(a01, tr0, w01[0]);  fma2(a23, tr0, w23[0]);
                fma2(a01, t1,  w01[1]);  fma2(a23, t1,  w23[1]);
                fma2(a01, t2,  w01[2]);  fma2(a23, t2,  w23[2]);
                tr0 = t2;
            }
            // r = 1
            {
                const float tb = pl1[(col + 1) * TT];
                const float tc = pl1[(col + 2) * TT];
                const unsigned long long t1 = pk2(tb, tb);
                const unsigned long long t2 = pk2(tc, tc);
                fma2(a01, tr1, w01[3]);  fma2(a23, tr1, w23[3]);
                fma2(a01, t1,  w01[4]);  fma2(a23, t1,  w23[4]);
                fma2(a01, t2,  w01[5]);  fma2(a23, t2,  w23[5]);
                tr1 = t2;
            }
            // r = 2
            {
                const float tb = pl2[(col + 1) * TT];
                const float tc = pl2[(col + 2) * TT];
                const unsigned long long t1 = pk2(tb, tb);
                const unsigned long long t2 = pk2(tc, tc);
                fma2(a01, tr2, w01[6]);  fma2(a23, tr2, w23[6]);
                fma2(a01, t1,  w01[7]);  fma2(a23, t1,  w23[7]);
                fma2(a01, t2,  w01[8]);  fma2(a23, t2,  w23[8]);
                tr2 = t2;
            }
            float4 zo;
            zo.x = f2lo(a01);  zo.y = f2hi(a01);
            zo.z = f2lo(a23);  zo.w = f2hi(a23);
            *(float4*)zr = zo;
        }
    }
    __syncwarp();   // z blocks below are warp-private

    // ---- PHASE 2: LIF scan. lane -> one of this warp's 32 (ch,wp) rows ----
    // banks = 4*(lane&7) + (lane>>3): perfect 0..31 cover, conflict-free.
    {
        const int csub = lane >> 3;            // channel within group
        const int wp   = lane & 7;
        const float* zr = zbuf + (cg * WPT + wp) * ZBLK + csub;
        float cur = 0.f, volt = 0.f;
        unsigned int bits = 0u;
        #pragma unroll
        for (int t = 0; t < TT; t++) {
            cur  = cur * 0.75f + zr[4 * t];
            volt = volt * 0.9f + cur;
            const bool s = volt >= 1.0f;
            bits |= s ? (1u << t) : 0u;
            volt  = s ? 0.f : volt;
        }
        sb[(4 * cg + csub) * WPT + wp] = bits;
    }
    __syncthreads();

    // ---- PHASE 3: coalesced epilogue. warp cg writes ch cg + 8*sp ----
    #pragma unroll
    for (int sp = 0; sp < 4; sp++) {
        const int ch = cg + 8 * sp;
        const float d  = delay[ch];           // warp-uniform
        const int   di = (int)floorf(d);
        const float f  = d - (float)di;
        const float onef = 1.0f - f;
        float* obase = out +
            (((size_t)((n * CHO + ch) * HP + hp) * WPX + wp0) * TT);
        #pragma unroll
        for (int i = 0; i < 2; i++) {
            const int idx = i * 32 + lane;    // 0..63 float4 slots (8wp x 8)
            const int wpi = idx >> 3;
            const int t   = (idx & 7) * 4;
            const unsigned int bt = sb[ch * WPT + wpi];
            unsigned int b0 = 0u, b1 = 0u;
            if (di >= 0 && di < 32)         b0 = bt << di;
            if (di + 1 >= 0 && di + 1 < 32) b1 = bt << (di + 1);
            float4 v;
            v.x = (((b0 >> (t + 0)) & 1u) ? onef : 0.f) + (((b1 >> (t + 0)) & 1u) ? f : 0.f);
            v.y = (((b0 >> (t + 1)) & 1u) ? onef : 0.f) + (((b1 >> (t + 1)) & 1u) ? f : 0.f);
            v.z = (((b0 >> (t + 2)) & 1u) ? onef : 0.f) + (((b1 >> (t + 2)) & 1u) ? f : 0.f);
            v.w = (((b0 >> (t + 3)) & 1u) ? onef : 0.f) + (((b1 >> (t + 3)) & 1u) ? f : 0.f);
            *(float4*)(obase + idx * 4) = v;
        }
    }
}

extern "C" void kernel_launch(void* const* d_in, const int* in_sizes, int n_in,
                              void* d_out, int out_size) {
    const float* spike    = (const float*)d_in[0];
    const float* weight_v = (const float*)d_in[1];
    const float* weight_g = (const float*)d_in[2];
    const float* delay    = (const float*)d_in[3];
    float* out = (float*)d_out;

    cudaFuncSetAttribute(snn_encoder_kernel,
                         cudaFuncAttributeMaxDynamicSharedMemorySize, SMEM_BYTES);
    dim3 grid(WPX / WPT, HP, NB);   // (8, 64, 8) = 4096 blocks
    snn_encoder_kernel<<<grid, NTHR, SMEM_BYTES>>>(spike, weight_v, weight_g, delay, out);
}

// round 13
// speedup vs baseline: 3.2701x; 1.1842x over previous
#include <cuda_runtime.h>

// Problem constants
#define NB     8
#define CIN    2
#define HIN    128
#define WIN    128
#define TT     32
#define CHO    32
#define HP     64
#define WPX    64
#define WPT    8             // wp columns per block
#define NTHR   256           // 8 warps: warp = 4 ch x 8 wp, lane = t
#define TILE_W 17            // 2*WPT + 1 halo

// smem layout (floats)
#define TILE_F  (CIN * 3 * TILE_W * TT)      // 3264 : input tile [6][17][32]
#define ZBLK    132                           // per-(cg,wp) z block: [t(32)][ch(4)]+pad
#define Z_OFF   TILE_F
#define Z_F     (8 * WPT * ZBLK)              // 8448
#define SW_OFF  (Z_OFF + Z_F)                 // weights [18][32]
#define SW_F    (18 * CHO)                    // 576
#define SB_OFF  (SW_OFF + SW_F)               // spike bitmasks [256]
#define SMEM_BYTES ((SB_OFF + 256) * 4)       // 50176 B ; x4 blocks = 200704 fits

// packed f32x2 fma: d = a*b + d
__device__ __forceinline__ void fma2(unsigned long long &d,
                                     unsigned long long a,
                                     unsigned long long b) {
    asm("fma.rn.f32x2 %0, %1, %2, %3;" : "=l"(d) : "l"(a), "l"(b), "l"(d));
}
// pack two floats into an f32x2 register pair {lo, hi}
__device__ __forceinline__ unsigned long long pk2(float lo, float hi) {
    unsigned long long r;
    asm("mov.b64 %0, {%1, %2};" : "=l"(r)
        : "r"(__float_as_uint(lo)), "r"(__float_as_uint(hi)));
    return r;
}
__device__ __forceinline__ float f2lo(unsigned long long v) {
    return __uint_as_float((unsigned)(v & 0xffffffffull));
}
__device__ __forceinline__ float f2hi(unsigned long long v) {
    return __uint_as_float((unsigned)(v >> 32));
}

__global__ __launch_bounds__(NTHR, 4)
void snn_encoder_kernel(const float* __restrict__ spike,
                        const float* __restrict__ weight_v,
                        const float* __restrict__ weight_g,
                        const float* __restrict__ delay,
                        float* __restrict__ out) {
    extern __shared__ __align__(16) float smem[];
    float* sin_ = smem;              // [plane(6)][w(17)][t(32)]
    float* zbuf = smem + Z_OFF;      // [(cg*8+wp)][132] = [t*4 + c]
    float* sw   = smem + SW_OFF;     // [tap(18)][ch(32)]
    unsigned int* sb = (unsigned int*)(smem + SB_OFF);   // sbits[256]

    const int tid  = threadIdx.x;
    const int lane = tid & 31;       // phase 1: lane = t
    const int cg   = tid >> 5;       // warp 0..7: channels 4*cg .. 4*cg+3
    const int wp0  = blockIdx.x * WPT;
    const int hp   = blockIdx.y;
    const int n    = blockIdx.z;

    // ---- cooperative input tile load via cp.async (LDGSTS): no reg roundtrip,
    // no per-thread long-scoreboard wait; OOB halo zero-filled by src-size=0 ----
    const int h0 = 2 * hp - 1;
    const int w0 = 2 * wp0 - 1;
    #pragma unroll
    for (int it = 0; it < 4; it++) {
        const int idx = tid + it * NTHR;
        if (idx < CIN * 3 * TILE_W * 8) {
            const int plane = idx / (TILE_W * 8);        // c*3 + r
            const int rem   = idx - plane * (TILE_W * 8);
            const int wj    = rem >> 3;
            const int t4    = rem & 7;
            const int c = plane / 3;
            const int r = plane - c * 3;
            const int h = h0 + r;
            const int w = w0 + wj;
            const bool ok = ((unsigned)h < HIN) && ((unsigned)w < WIN);
            const float* src = spike +
                (((size_t)(n * CIN + c) * HIN + (ok ? h : 0)) * WIN + (ok ? w : 0)) * TT
                + t4 * 4;
            const unsigned int dst = (unsigned int)__cvta_generic_to_shared(
                sin_ + (plane * TILE_W + wj) * TT + t4 * 4);
            const int sz = ok ? 16 : 0;
            asm volatile("cp.async.cg.shared.global [%0], [%1], 16, %2;"
                         :: "r"(dst), "l"(src), "r"(sz));
        }
    }
    asm volatile("cp.async.commit_group;");

    // ---- weight norm (one thread per output channel), overlaps cp.async ----
    if (tid < 32) {
        float wv[18];
        float ss = 0.f;
        #pragma unroll
        for (int k = 0; k < 18; k++) {
            wv[k] = weight_v[tid * 18 + k];
            ss += wv[k] * wv[k];
        }
        const float sc = weight_g[tid] / sqrtf(ss);
        #pragma unroll
        for (int k = 0; k < 18; k++)
            sw[k * 32 + tid] = wv[k] * sc;
    }

    asm volatile("cp.async.wait_group 0;");
    __syncthreads();

    // ---- PHASE 1: conv. warp = 4 ch x 8 wp, lane = t.
    // Two 9-tap passes over input channel c (36 weight regs each; fits 64-reg
    // cap). kw-rolling tap reuse. z stored channel-interleaved: one STS.128
    // per (j, pass); pass 2 does LDS.128 + STS.128. Summation order k=0..17
    // per accumulator unchanged -> z bit-identical to round 12.
    #pragma unroll 1
    for (int cpass = 0; cpass < CIN; cpass++) {
        unsigned long long w01[9], w23[9];
        #pragma unroll
        for (int k = 0; k < 9; k++) {
            const float4 wv = *(const float4*)(sw + (9 * cpass + k) * 32 + 4 * cg);
            w01[k] = pk2(wv.x, wv.y);
            w23[k] = pk2(wv.z, wv.w);
        }
        const float* pl0 = sin_ + (3 * cpass + 0) * TILE_W * TT + lane;
        const float* pl1 = sin_ + (3 * cpass + 1) * TILE_W * TT + lane;
        const float* pl2 = sin_ + (3 * cpass + 2) * TILE_W * TT + lane;
        // rolling kw=0 taps (dup'd) for r = 0,1,2
        float s0 = pl0[0];
        float s1 = pl1[0];
        float s2 = pl2[0];
        unsigned long long tr0 = pk2(s0, s0);
        unsigned long long tr1 = pk2(s1, s1);
        unsigned long long tr2 = pk2(s2, s2);
        #pragma unroll
        for (int j = 0; j < 8; j++) {
            const int col = 2 * j;
            float* zr = zbuf + (cg * WPT + j) * ZBLK + 4 * lane;
            unsigned long long a01, a23;
            if (cpass == 0) { a01 = 0ull; a23 = 0ull; }
            else {
                const float4 zp = *(const float4*)zr;
                a01 = pk2(zp.x, zp.y);
                a23 = pk2(zp.z, zp.w);
            }
            // r = 0
            {
                const float tb = pl0[(col + 1) * TT];
                const float tc = pl0[(col + 2) * TT];
                const unsigned long long t1 = pk2(tb, tb);
                const unsigned long long t2 = pk2(tc, tc);
                fma2(a01, tr0, w01[0]);  fma2(a23, tr0, w23[0]);
                fma2(a01, t1,  w01[1]);  fma2(a23, t1,  w23[1]);
                fma2(a01, t2,  w01[2]);  fma2(a23, t2,  w23[2]);
                tr0 = t2;
            }
            // r = 1
            {
                const float tb = pl1[(col + 1) * TT];
                const float tc = pl1[(col + 2) * TT];
                const unsigned long long t1 = pk2(tb, tb);
                const unsigned long long t2 = pk2(tc, tc);
                fma2(a01, tr1, w01[3]);  fma2(a23, tr1, w23[3]);
                fma2(a01, t1,  w01[4]);  fma2(a23, t1,  w23[4]);
                fma2(a01, t2,  w01[5]);  fma2(a23, t2,  w23[5]);
                tr1 = t2;
            }
            // r = 2
            {
                const float tb = pl2[(col + 1) * TT];
                const float tc = pl2[(col + 2) * TT];
                const unsigned long long t1 = pk2(tb, tb);
                const unsigned long long t2 = pk2(tc, tc);
                fma2(a01, tr2, w01[6]);  fma2(a23, tr2, w23[6]);
                fma2(a01, t1,  w01[7]);  fma2(a23, t1,  w23[7]);
                fma2(a01, t2,  w01[8]);  fma2(a23, t2,  w23[8]);
                tr2 = t2;
            }
            float4 zo;
            zo.x = f2lo(a01);  zo.y = f2hi(a01);
            zo.z = f2lo(a23);  zo.w = f2hi(a23);
            *(float4*)zr = zo;
        }
    }
    __syncwarp();   // z blocks below are warp-private

    // ---- PHASE 2: LIF scan. lane -> one of this warp's 32 (ch,wp) rows ----
    // banks = 4*(lane&7) + (lane>>3): perfect 0..31 cover, conflict-free.
    {
        const int csub = lane >> 3;            // channel within group
        const int wp   = lane & 7;
        const float* zr = zbuf + (cg * WPT + wp) * ZBLK + csub;
        float cur = 0.f, volt = 0.f;
        unsigned int bits = 0u;
        #pragma unroll
        for (int t = 0; t < TT; t++) {
            cur  = cur * 0.75f + zr[4 * t];
            volt = volt * 0.9f + cur;
            const bool s = volt >= 1.0f;
            bits |= s ? (1u << t) : 0u;
            volt  = s ? 0.f : volt;
        }
        sb[(4 * cg + csub) * WPT + wp] = bits;
    }
    __syncthreads();

    // ---- PHASE 3: coalesced epilogue. warp cg writes ch cg + 8*sp ----
    #pragma unroll
    for (int sp = 0; sp < 4; sp++) {
        const int ch = cg + 8 * sp;
        const float d  = delay[ch];           // warp-uniform
        const int   di = (int)floorf(d);
        const float f  = d - (float)di;
        const float onef = 1.0f - f;
        float* obase = out +
            (((size_t)((n * CHO + ch) * HP + hp) * WPX + wp0) * TT);
        #pragma unroll
        for (int i = 0; i < 2; i++) {
            const int idx = i * 32 + lane;    // 0..63 float4 slots (8wp x 8)
            const int wpi = idx >> 3;
            const int t   = (idx & 7) * 4;
            const unsigned int bt = sb[ch * WPT + wpi];
            unsigned int b0 = 0u, b1 = 0u;
            if (di >= 0 && di < 32)         b0 = bt << di;
            if (di + 1 >= 0 && di + 1 < 32) b1 = bt << (di + 1);
            float4 v;
            v.x = (((b0 >> (t + 0)) & 1u) ? onef : 0.f) + (((b1 >> (t + 0)) & 1u) ? f : 0.f);
            v.y = (((b0 >> (t + 1)) & 1u) ? onef : 0.f) + (((b1 >> (t + 1)) & 1u) ? f : 0.f);
            v.z = (((b0 >> (t + 2)) & 1u) ? onef : 0.f) + (((b1 >> (t + 2)) & 1u) ? f : 0.f);
            v.w = (((b0 >> (t + 3)) & 1u) ? onef : 0.f) + (((b1 >> (t + 3)) & 1u) ? f : 0.f);
            *(float4*)(obase + idx * 4) = v;
        }
    }
}

extern "C" void kernel_launch(void* const* d_in, const int* in_sizes, int n_in,
                              void* d_out, int out_size) {
    const float* spike    = (const float*)d_in[0];
    const float* weight_v = (const float*)d_in[1];
    const float* weight_g = (const float*)d_in[2];
    const float* delay    = (const float*)d_in[3];
    float* out = (float*)d_out;

    cudaFuncSetAttribute(snn_encoder_kernel,
                         cudaFuncAttributeMaxDynamicSharedMemorySize, SMEM_BYTES);
    dim3 grid(WPX / WPT, HP, NB);   // (8, 64, 8) = 4096 blocks
    snn_encoder_kernel<<<grid, NTHR, SMEM_BYTES>>>(spike, weight_v, weight_g, delay, out);
}